// round 4
// baseline (speedup 1.0000x reference)
#include <cuda_runtime.h>
#include <math.h>

#define EPS 1e-5f

// ---------------- packed f32x2 helpers ----------------
__device__ __forceinline__ unsigned long long pk2(float lo, float hi) {
    unsigned long long r;
    asm("mov.b64 %0, {%1, %2};" : "=l"(r) : "f"(lo), "f"(hi));
    return r;
}
__device__ __forceinline__ void upk2(unsigned long long v, float& lo, float& hi) {
    asm("mov.b64 {%0, %1}, %2;" : "=f"(lo), "=f"(hi) : "l"(v));
}
__device__ __forceinline__ unsigned long long ffma2(unsigned long long a,
                                                    unsigned long long b,
                                                    unsigned long long c) {
    unsigned long long d;
    asm("fma.rn.f32x2 %0, %1, %2, %3;" : "=l"(d) : "l"(a), "l"(b), "l"(c));
    return d;
}

// ---------------- static scratch ----------------
__device__ float g_t1[2*128*64*64];
__device__ float g_part[4*128*64*64];
__device__ float g_t2[2*128*64*64];
__device__ float g_g2[2*128*128*128];
__device__ float g_K1[2*9*128*128];
__device__ float g_M1[2*9*64*64*64];
__device__ float g_y1[2*64*128*128];
__device__ float g_g1[2*64*256*256];
__device__ float g_K2[2*9*256*256];
__device__ float g_M2[2*9*32*128*128];
__device__ float g_y2[2*32*256*256];
__device__ float g_mean[1024];
__device__ float g_var[1024];
__device__ float g_na[1024];
__device__ float g_nc[1024];

// ---------------- instance stats ----------------
__global__ void stats_kernel(const float* __restrict__ x, int HW,
                             float* __restrict__ mean, float* __restrict__ var) {
    int bc = blockIdx.x;
    const float* p = x + (size_t)bc * HW;
    float s = 0.f, ss = 0.f;
    for (int i = threadIdx.x; i < HW; i += blockDim.x) {
        float v = p[i]; s += v; ss += v * v;
    }
    __shared__ float sh0[32], sh1[32];
    for (int o = 16; o; o >>= 1) {
        s  += __shfl_down_sync(0xffffffffu, s, o);
        ss += __shfl_down_sync(0xffffffffu, ss, o);
    }
    int wid = threadIdx.x >> 5, lid = threadIdx.x & 31;
    if (lid == 0) { sh0[wid] = s; sh1[wid] = ss; }
    __syncthreads();
    if (wid == 0) {
        int nw = blockDim.x >> 5;
        s  = (lid < nw) ? sh0[lid] : 0.f;
        ss = (lid < nw) ? sh1[lid] : 0.f;
        for (int o = 16; o; o >>= 1) {
            s  += __shfl_down_sync(0xffffffffu, s, o);
            ss += __shfl_down_sync(0xffffffffu, ss, o);
        }
        if (lid == 0) {
            float m = s / (float)HW;
            mean[bc] = m;
            var[bc]  = ss / (float)HW - m * m;
        }
    }
}

__global__ void inorm_coef(const float* __restrict__ mean, const float* __restrict__ var,
                           float* __restrict__ a, float* __restrict__ c, int n) {
    int i = blockIdx.x * blockDim.x + threadIdx.x;
    if (i < n) {
        float r = rsqrtf(var[i] + EPS);
        a[i] = r; c[i] = -mean[i] * r;
    }
}

__global__ void dinorm_coef(const float* __restrict__ mean, const float* __restrict__ var,
                            float* __restrict__ a, float* __restrict__ c, int n) {
    int i = blockIdx.x * blockDim.x + threadIdx.x;
    if (i < n) {
        float m = mean[i], v = var[i];
        float r1 = rsqrtf(v + EPS);
        float a1 = 1.f + r1, c1 = -m * r1;
        float m2 = a1 * m + c1;
        float v2 = a1 * a1 * v;
        float r2 = rsqrtf(v2 + EPS);
        a[i] = a1 * (1.f + r2);
        c[i] = c1 * (1.f + r2) - m2 * r2;
    }
}

// ---------------- register-tiled 3x3 conv, f32x2 ----------------
// block (16,8)=128 thr; tile 32 wide x (8*PXH) tall; thread: 2 cols x PXH rows.
template<int CO_BLK, int PXH, int CI_SPLIT, bool BIAS>
__global__ void __launch_bounds__(128) conv3x3_v3(
        const float* __restrict__ in, const float* __restrict__ w,
        const float* __restrict__ bias, float* __restrict__ out,
        int Ci, int Co, int Hs, int Ws,
        const float* __restrict__ na, const float* __restrict__ nc) {
    const int TW = 32, TH = 8 * PXH;
    int tiles_x = Ws / TW;
    int tx0 = (blockIdx.x % tiles_x) * TW;
    int ty0 = (blockIdx.x / tiles_x) * TH;
    int co0 = blockIdx.y * CO_BLK;
    int zz = blockIdx.z;
    int b = zz / CI_SPLIT;
    int gsp = zz % CI_SPLIT;
    int ciN = Ci / CI_SPLIT;
    int ci0 = gsp * ciN;
    int lx = threadIdx.x, ly = threadIdx.y;
    int tid = ly * 16 + lx;

    __shared__ float xs[TH + 2][TW + 4];
    __shared__ unsigned long long ws2[CO_BLK][9];

    unsigned long long accp[CO_BLK][PXH];
    #pragma unroll
    for (int u = 0; u < CO_BLK; u++)
        #pragma unroll
        for (int r = 0; r < PXH; r++) accp[u][r] = 0ull;

    const float* inb = in + ((size_t)b * Ci + ci0) * Hs * Ws;
    for (int ci = 0; ci < ciN; ci++) {
        const float* inc = inb + (size_t)ci * Hs * Ws;
        float aa = 1.f, cc0 = 0.f;
        if (na) { aa = na[b * Ci + ci0 + ci]; cc0 = nc[b * Ci + ci0 + ci]; }
        #pragma unroll 4
        for (int i = tid; i < (TH + 2) * (TW + 2); i += 128) {
            int r = i / (TW + 2), c = i % (TW + 2);
            int gy = ty0 + r - 1, gx = tx0 + c - 1;
            float v = 0.f;
            if ((unsigned)gy < (unsigned)Hs && (unsigned)gx < (unsigned)Ws)
                v = fmaf(aa, inc[gy * Ws + gx], cc0);
            xs[r][c] = v;
        }
        if (tid < CO_BLK * 9) {
            float wv = w[((size_t)(co0 + tid / 9) * Ci + ci0 + ci) * 9 + tid % 9];
            ws2[tid / 9][tid % 9] = pk2(wv, wv);
        }
        __syncthreads();

        unsigned long long xp[PXH + 2][3];
        #pragma unroll
        for (int r = 0; r < PXH + 2; r++) {
            float x0 = xs[ly * PXH + r][2 * lx];
            float x1 = xs[ly * PXH + r][2 * lx + 1];
            float x2 = xs[ly * PXH + r][2 * lx + 2];
            float x3 = xs[ly * PXH + r][2 * lx + 3];
            xp[r][0] = pk2(x0, x1);
            xp[r][1] = pk2(x1, x2);
            xp[r][2] = pk2(x2, x3);
        }

        #pragma unroll
        for (int u = 0; u < CO_BLK; u++) {
            #pragma unroll
            for (int i = 0; i < 3; i++)
                #pragma unroll
                for (int j = 0; j < 3; j++) {
                    unsigned long long wv2 = ws2[u][i * 3 + j];
                    #pragma unroll
                    for (int r = 0; r < PXH; r++)
                        accp[u][r] = ffma2(xp[i + r][j], wv2, accp[u][r]);
                }
        }
        __syncthreads();
    }

    int oy = ty0 + ly * PXH, ox = tx0 + 2 * lx;
    #pragma unroll
    for (int u = 0; u < CO_BLK; u++) {
        float bv = BIAS ? bias[co0 + u] : 0.f;
        #pragma unroll
        for (int r = 0; r < PXH; r++) {
            float a0, a1;
            upk2(accp[u][r], a0, a1);
            float* op = out + (((size_t)zz * Co + co0 + u) * Hs + oy + r) * Ws + ox;
            *(float2*)op = make_float2(a0 + bv, a1 + bv);
        }
    }
}

// reduce 2 ci-split partials + bias
__global__ void reduce2_bias(const float* __restrict__ p, const float* __restrict__ bias,
                             float* __restrict__ out, int Co, int HW, int N) {
    int i = blockIdx.x * 256 + threadIdx.x;
    if (i >= N) return;
    int b = i / (Co * HW);
    int rem = i - b * Co * HW;
    int co = rem / HW;
    out[i] = p[(size_t)(2 * b) * Co * HW + rem] + p[(size_t)(2 * b + 1) * Co * HW + rem] + bias[co];
}

// ---------------- 1x1 conv + residual, f32x2 ----------------
__global__ void __launch_bounds__(128) conv1x1_res4(
        const float* __restrict__ x, const float* __restrict__ w,
        const float* __restrict__ bias, float* __restrict__ out,
        int Cc, int HW4) {
    int p = blockIdx.x * 128 + threadIdx.x;
    int o0 = blockIdx.y * 8;
    int b = blockIdx.z;
    __shared__ unsigned long long ws2[8 * 128];
    for (int i = threadIdx.x; i < 8 * Cc; i += 128) {
        float wv = w[(o0 + i / Cc) * Cc + i % Cc];
        ws2[i] = pk2(wv, wv);
    }
    __syncthreads();
    union F4 { float4 f; unsigned long long u[2]; };
    const float4* xb = (const float4*)x + (size_t)b * Cc * HW4;
    unsigned long long acc[8][2];
    #pragma unroll
    for (int u = 0; u < 8; u++) { acc[u][0] = 0ull; acc[u][1] = 0ull; }
    for (int ci = 0; ci < Cc; ci++) {
        F4 xv; xv.f = xb[(size_t)ci * HW4 + p];
        #pragma unroll
        for (int u = 0; u < 8; u++) {
            unsigned long long wv2 = ws2[u * Cc + ci];
            acc[u][0] = ffma2(wv2, xv.u[0], acc[u][0]);
            acc[u][1] = ffma2(wv2, xv.u[1], acc[u][1]);
        }
    }
    float4* ob = (float4*)out + (size_t)b * Cc * HW4;
    #pragma unroll
    for (int u = 0; u < 8; u++) {
        float bv = bias[o0 + u];
        float4 rv = xb[(size_t)(o0 + u) * HW4 + p];
        F4 a; a.u[0] = acc[u][0]; a.u[1] = acc[u][1];
        float4 o;
        o.x = a.f.x + bv + rv.x;
        o.y = a.f.y + bv + rv.y;
        o.z = a.f.z + bv + rv.z;
        o.w = a.f.w + bv + rv.w;
        ob[(size_t)(o0 + u) * HW4 + p] = o;
    }
}

// ---------------- PAC gaussian kernel ----------------
__global__ void pac_kernel_K(const float* __restrict__ g, float* __restrict__ K,
                             int Cg, int Hg, int Wg) {
    int tiles_x = Wg / 16;
    int tx0 = (blockIdx.x % tiles_x) * 16, ty0 = (blockIdx.x / tiles_x) * 16;
    int b = blockIdx.y;
    int lx = threadIdx.x, ly = threadIdx.y;
    int tid = ly * 16 + lx;
    __shared__ float gs[18][19];
    float acc[9];
    #pragma unroll
    for (int k = 0; k < 9; k++) acc[k] = 0.f;
    const float* gb = g + (size_t)b * Cg * Hg * Wg;
    for (int c = 0; c < Cg; c++) {
        const float* gc = gb + (size_t)c * Hg * Wg;
        #pragma unroll
        for (int i = tid; i < 18 * 18; i += 256) {
            int r = i / 18, cx = i % 18;
            int yy = ty0 + r - 1, xx = tx0 + cx - 1;
            gs[r][cx] = (yy >= 0 && yy < Hg && xx >= 0 && xx < Wg) ? gc[yy * Wg + xx] : 0.f;
        }
        __syncthreads();
        float ctr = gs[ly + 1][lx + 1];
        #pragma unroll
        for (int i = 0; i < 3; i++)
            #pragma unroll
            for (int j = 0; j < 3; j++) {
                float d = gs[ly + i][lx + j] - ctr;
                acc[i * 3 + j] = fmaf(d, d, acc[i * 3 + j]);
            }
        __syncthreads();
    }
    size_t base = ((size_t)b * 9) * Hg * Wg + (size_t)(ty0 + ly) * Wg + tx0 + lx;
    #pragma unroll
    for (int k = 0; k < 9; k++)
        K[base + (size_t)k * Hg * Wg] = __expf(-0.5f * acc[k]);
}

// ---------------- tap GEMM, f32x2 ----------------
// M[b][k*Co+co][p] = sum_ci w[ci,co,k] * x[b,ci,p]; optional per-(b,ci) input affine.
__global__ void __launch_bounds__(128) tap_gemm(
        const float* __restrict__ x, const float* __restrict__ w,
        float* __restrict__ M, int Cin, int Co, int HW4,
        const float* __restrict__ na, const float* __restrict__ nc) {
    int p = blockIdx.x * 256 + threadIdx.x;
    int kc0 = blockIdx.y * 8;
    int b = blockIdx.z;
    int k = kc0 / Co, co0 = kc0 % Co;
    __shared__ unsigned long long ws2[8 * 128];
    for (int i = threadIdx.x; i < 8 * Cin; i += 128) {
        int u = i / Cin, ci = i % Cin;
        float wv = w[((size_t)ci * Co + co0 + u) * 9 + k];
        ws2[i] = pk2(wv, wv);
    }
    __syncthreads();
    union F4 { float4 f; unsigned long long u[2]; };
    const float4* xb = (const float4*)x + (size_t)b * Cin * HW4;
    unsigned long long a0[8][2], a1[8][2];
    #pragma unroll
    for (int u = 0; u < 8; u++) { a0[u][0] = a0[u][1] = 0ull; a1[u][0] = a1[u][1] = 0ull; }
    for (int ci = 0; ci < Cin; ci++) {
        F4 x0, x1;
        x0.f = xb[(size_t)ci * HW4 + p];
        x1.f = xb[(size_t)ci * HW4 + p + 128];
        if (na) {
            unsigned long long aa2 = pk2(na[b * Cin + ci], na[b * Cin + ci]);
            unsigned long long cc2 = pk2(nc[b * Cin + ci], nc[b * Cin + ci]);
            x0.u[0] = ffma2(aa2, x0.u[0], cc2);
            x0.u[1] = ffma2(aa2, x0.u[1], cc2);
            x1.u[0] = ffma2(aa2, x1.u[0], cc2);
            x1.u[1] = ffma2(aa2, x1.u[1], cc2);
        }
        #pragma unroll
        for (int u = 0; u < 8; u++) {
            unsigned long long wv2 = ws2[u * Cin + ci];
            a0[u][0] = ffma2(wv2, x0.u[0], a0[u][0]);
            a0[u][1] = ffma2(wv2, x0.u[1], a0[u][1]);
            a1[u][0] = ffma2(wv2, x1.u[0], a1[u][0]);
            a1[u][1] = ffma2(wv2, x1.u[1], a1[u][1]);
        }
    }
    float4* Mb = (float4*)M + (size_t)b * 9 * Co * HW4;
    #pragma unroll
    for (int u = 0; u < 8; u++) {
        F4 o0, o1;
        o0.u[0] = a0[u][0]; o0.u[1] = a0[u][1];
        o1.u[0] = a1[u][0]; o1.u[1] = a1[u][1];
        Mb[(size_t)(kc0 + u) * HW4 + p] = o0.f;
        Mb[(size_t)(kc0 + u) * HW4 + p + 128] = o1.f;
    }
}

// ---------------- PAC combine ----------------
template<int CO_T>
__global__ void pac_combine(const float* __restrict__ M, const float* __restrict__ K,
                            const float* __restrict__ bias, float* __restrict__ out,
                            int Co, int Hs, int Ws) {
    int Ho = 2 * Hs, Wo = 2 * Ws;
    int px = blockIdx.x * 256 + threadIdx.x;
    int h = px / Wo, w = px % Wo;
    int co0 = blockIdx.y * CO_T;
    int b = blockIdx.z;

    float acc[CO_T];
    #pragma unroll
    for (int u = 0; u < CO_T; u++) acc[u] = bias[co0 + u];

    int nr, ry[2], rk[2];
    if (h & 1) {
        nr = 2; rk[0] = 0; ry[0] = (h - 1) >> 1; rk[1] = 2; ry[1] = (h + 1) >> 1;
        if (ry[1] >= Hs) nr = 1;
    } else { nr = 1; rk[0] = 1; ry[0] = h >> 1; }
    int ncn, cx[2], ck[2];
    if (w & 1) {
        ncn = 2; ck[0] = 0; cx[0] = (w - 1) >> 1; ck[1] = 2; cx[1] = (w + 1) >> 1;
        if (cx[1] >= Ws) ncn = 1;
    } else { ncn = 1; ck[0] = 1; cx[0] = w >> 1; }

    const float* Kb = K + (size_t)b * 9 * Ho * Wo + px;
    const float* Mb = M + (size_t)b * 9 * Co * Hs * Ws;
    int HsWs = Hs * Ws;
    for (int rr = 0; rr < nr; rr++)
        for (int cc = 0; cc < ncn; cc++) {
            int k = rk[rr] * 3 + ck[cc];
            float Kv = __ldg(Kb + (size_t)k * Ho * Wo);
            const float* Mp = Mb + ((size_t)k * Co + co0) * HsWs + ry[rr] * Ws + cx[cc];
            #pragma unroll
            for (int u = 0; u < CO_T; u++)
                acc[u] = fmaf(Kv, __ldg(Mp + (size_t)u * HsWs), acc[u]);
        }
    #pragma unroll
    for (int u = 0; u < CO_T; u++)
        out[(((size_t)b * Co + co0 + u) * Ho + h) * Wo + w] = acc[u];
}

// ---------------- driver ----------------
extern "C" void kernel_launch(void* const* d_in, const int* in_sizes, int n_in,
                              void* d_out, int out_size) {
    const float* x      = (const float*)d_in[0];
    const float* ef2    = (const float*)d_in[1];
    const float* ef1    = (const float*)d_in[2];
    const float* W_down = (const float*)d_in[3];
    const float* b_down = (const float*)d_in[4];
    const float* W_mid  = (const float*)d_in[5];
    const float* b_mid  = (const float*)d_in[6];
    const float* W_adj2 = (const float*)d_in[7];
    const float* b_adj2 = (const float*)d_in[8];
    const float* W_adj1 = (const float*)d_in[9];
    const float* b_adj1 = (const float*)d_in[10];
    const float* W16    = (const float*)d_in[11];
    const float* b16    = (const float*)d_in[12];
    const float* W20    = (const float*)d_in[13];
    const float* b20    = (const float*)d_in[14];
    const float* W24    = (const float*)d_in[15];
    const float* b24    = (const float*)d_in[16];
    float* out = (float*)d_out;

    float *t1, *part, *t2, *g2, *K1, *M1, *y1, *g1, *K2, *M2, *y2, *mean, *var, *na, *nc;
    cudaGetSymbolAddress((void**)&t1, g_t1);
    cudaGetSymbolAddress((void**)&part, g_part);
    cudaGetSymbolAddress((void**)&t2, g_t2);
    cudaGetSymbolAddress((void**)&g2, g_g2);
    cudaGetSymbolAddress((void**)&K1, g_K1);
    cudaGetSymbolAddress((void**)&M1, g_M1);
    cudaGetSymbolAddress((void**)&y1, g_y1);
    cudaGetSymbolAddress((void**)&g1, g_g1);
    cudaGetSymbolAddress((void**)&K2, g_K2);
    cudaGetSymbolAddress((void**)&M2, g_M2);
    cudaGetSymbolAddress((void**)&y2, g_y2);
    cudaGetSymbolAddress((void**)&mean, g_mean);
    cudaGetSymbolAddress((void**)&var, g_var);
    cudaGetSymbolAddress((void**)&na, g_na);
    cudaGetSymbolAddress((void**)&nc, g_nc);

    dim3 cblk(16, 8);
    dim3 blk16(16, 16);

    // 1) inorm(x) coefficients
    stats_kernel<<<512, 256>>>(x, 64 * 64, mean, var);
    inorm_coef<<<2, 256>>>(mean, var, na, nc, 512);

    // 2) conv_down 256->128 @64x64, norm fused, Ci split G=2 -> partials, then reduce
    conv3x3_v3<8, 2, 2, false><<<dim3(8, 16, 4), cblk>>>(x, W_down, b_down, part,
                                                         256, 128, 64, 64, na, nc);
    reduce2_bias<<<4096, 256>>>(part, b_down, t1, 128, 64 * 64, 2 * 128 * 64 * 64);

    // 3) 1x1 + residual
    conv1x1_res4<<<dim3(8, 16, 2), 128>>>(t1, W_mid, b_mid, t2, 128, 1024);

    // 4) g2 = adjust_ef_lv2: 64->128 @128x128
    conv3x3_v3<8, 4, 1, true><<<dim3(16, 16, 2), cblk>>>(ef2, W_adj2, b_adj2, g2,
                                                         64, 128, 128, 128,
                                                         (const float*)0, (const float*)0);

    // 5) PAC kernel 1
    pac_kernel_K<<<dim3(64, 2), blk16>>>(g2, K1, 128, 128, 128);

    // 6) pacT1 = tap GEMM + combine: 128->64, 64x64 -> 128x128
    tap_gemm<<<dim3(4, 72, 2), 128>>>(t2, W16, M1, 128, 64, 1024,
                                      (const float*)0, (const float*)0);
    pac_combine<8><<<dim3(64, 8, 2), 256>>>(M1, K1, b16, y1, 64, 64, 64);

    // 7) dinorm coefs for y1 (affine fused into next tap_gemm)
    stats_kernel<<<128, 256>>>(y1, 128 * 128, mean, var);
    dinorm_coef<<<1, 256>>>(mean, var, na, nc, 128);

    // 8) g1 = adjust_ef_lv1: 32->64 @256x256
    conv3x3_v3<8, 4, 1, true><<<dim3(64, 8, 2), cblk>>>(ef1, W_adj1, b_adj1, g1,
                                                        32, 64, 256, 256,
                                                        (const float*)0, (const float*)0);

    // 9) PAC kernel 2
    pac_kernel_K<<<dim3(256, 2), blk16>>>(g1, K2, 64, 256, 256);

    // 10) pacT2 = tap GEMM (y1 affine fused) + combine: 64->32, 128x128 -> 256x256
    tap_gemm<<<dim3(16, 36, 2), 128>>>(y1, W20, M2, 64, 32, 4096, na, nc);
    pac_combine<8><<<dim3(256, 4, 2), 256>>>(M2, K2, b20, y2, 32, 128, 128);

    // 11) dinorm coefs for y2 (affine fused into final conv)
    stats_kernel<<<64, 256>>>(y2, 256 * 256, mean, var);
    dinorm_coef<<<1, 64>>>(mean, var, na, nc, 64);

    // 12) final conv 32->3 @256x256 (y2 affine fused)
    conv3x3_v3<3, 2, 1, true><<<dim3(128, 1, 2), cblk>>>(y2, W24, b24, out,
                                                         32, 3, 256, 256, na, nc);
}